// round 1
// baseline (speedup 1.0000x reference)
#include <cuda_runtime.h>
#include <cuda_bf16.h>

// DirectVoxGO Raw2Alpha + Alphas2Weights fused, sorted-segment version.
//
// Inputs (metadata order):
//   d_in[0]: density  float32 [M]
//   d_in[1]: ray_id   int32   [M]   (sorted ascending)
//   d_in[2]: N        int32   [1]   (recovered on host as out_size - M instead)
// Output: d_out float32 [M + N] = concat(weights[M], alphainv_last[N])

#define ALPHA_INIT   1e-4f
#define SHIFT_F      (-9.2102403669758f)   // log(1/(1-1e-4) - 1)
#define INTERVAL_F   0.5f

#define MAX_RAYS_P1  (1 << 20)             // generous static bound for N+1

// Scratch: segment start offsets, start[r] = first index with ray_id >= r,
// start[N] = M. Static __device__ array (no allocation allowed).
__device__ int g_start[MAX_RAYS_P1 + 1];

// ---------------------------------------------------------------------------
// Pass 1: segment boundaries from the sorted ray_id array.
// ---------------------------------------------------------------------------
__global__ __launch_bounds__(256) void seg_bounds_kernel(
    const int* __restrict__ ray_id, int M, int N)
{
    int i = blockIdx.x * blockDim.x + threadIdx.x;
    if (i >= M) return;

    int cur  = ray_id[i];
    int prev = (i == 0) ? -1 : ray_id[i - 1];

    // Fill starts for every ray id in (prev, cur]. Gaps are tiny (ids are a
    // sorted sample of [0,N)), so this loop is ~1 iteration on average.
    for (int r = prev + 1; r <= cur; ++r) g_start[r] = i;

    // Tail: rays after the last present id (and the N sentinel) start at M.
    if (i == M - 1) {
        for (int r = cur + 1; r <= N; ++r) g_start[r] = M;
    }
}

// ---------------------------------------------------------------------------
// Pass 2: one warp per ray. Segmented inclusive scan of softplus via warp
// shuffles with a running carry; emit weights and the final transmittance.
// ---------------------------------------------------------------------------
__global__ __launch_bounds__(256) void seg_scan_kernel(
    const float* __restrict__ density,
    float* __restrict__ out_weights,
    float* __restrict__ out_alphainv,
    int N)
{
    const int warps_per_block = blockDim.x >> 5;
    const int ray  = blockIdx.x * warps_per_block + (threadIdx.x >> 5);
    const int lane = threadIdx.x & 31;
    if (ray >= N) return;

    const int s = g_start[ray];
    const int e = g_start[ray + 1];

    float carry = 0.0f;   // inclusive prefix of sp entering this chunk

    for (int base = s; base < e; base += 32) {
        const int i = base + lane;

        float sp = 0.0f;
        if (i < e) {
            float x = density[i] + SHIFT_F;
            // numerically stable softplus: max(x,0) + log1p(exp(-|x|))
            sp = fmaxf(x, 0.0f) + log1pf(__expf(-fabsf(x)));
        }

        // warp inclusive scan of sp
        float inc = sp;
        #pragma unroll
        for (int d = 1; d < 32; d <<= 1) {
            float v = __shfl_up_sync(0xffffffffu, inc, d);
            if (lane >= d) inc += v;
        }
        inc += carry;

        if (i < e) {
            const float excl  = inc - sp;                       // exclusive prefix
            const float T     = __expf(-excl * INTERVAL_F);      // transmittance
            const float alpha = 1.0f - __expf(-sp * INTERVAL_F); // Raw2Alpha
            out_weights[i] = alpha * T;
        }

        // lane 31 holds the inclusive total through this chunk (invalid lanes
        // contributed sp = 0, so a partial final chunk is still correct)
        carry = __shfl_sync(0xffffffffu, inc, 31);
    }

    if (lane == 0) {
        out_alphainv[ray] = __expf(-carry * INTERVAL_F);
    }
}

// ---------------------------------------------------------------------------
extern "C" void kernel_launch(void* const* d_in, const int* in_sizes, int n_in,
                              void* d_out, int out_size)
{
    const float* density = (const float*)d_in[0];
    const int*   ray_id  = (const int*)d_in[1];

    const int M = in_sizes[0];
    const int N = out_size - M;   // weights[M] ++ alphainv_last[N]

    float* out_weights  = (float*)d_out;
    float* out_alphainv = (float*)d_out + M;

    // Pass 1: boundaries
    {
        const int threads = 256;
        const int blocks  = (M + threads - 1) / threads;
        seg_bounds_kernel<<<blocks, threads>>>(ray_id, M, N);
    }

    // Pass 2: warp-per-ray segmented scan
    {
        const int threads = 256;                 // 8 warps / block
        const int warps_per_block = threads / 32;
        const int blocks = (N + warps_per_block - 1) / warps_per_block;
        seg_scan_kernel<<<blocks, threads>>>(density, out_weights, out_alphainv, N);
    }
}

// round 4
// speedup vs baseline: 1.4578x; 1.4578x over previous
#include <cuda_runtime.h>
#include <cuda_bf16.h>

// DirectVoxGO Raw2Alpha + Alphas2Weights fused, sorted-segment version (R4).
//
// Inputs (metadata order):
//   d_in[0]: density  float32 [M]
//   d_in[1]: ray_id   int32   [M]   (sorted ascending)
// Output: d_out float32 [M + N] = concat(weights[M], alphainv_last[N])

#define SHIFT_F      (-9.2102403669758f)   // log(1/(1-1e-4) - 1)
#define INTERVAL_F   0.5f

#define MAX_RAYS_P1  (1 << 20)             // generous static bound for N+1

__device__ int g_start[MAX_RAYS_P1 + 1];

// ---------------------------------------------------------------------------
// Pass 1: segment boundaries, 4 elements per thread via int4.
// ---------------------------------------------------------------------------
__global__ __launch_bounds__(256) void seg_bounds_kernel(
    const int* __restrict__ ray_id, int M, int N)
{
    const int t  = blockIdx.x * blockDim.x + threadIdx.x;
    const int i0 = t * 4;
    if (i0 >= M) return;

    int ids[4];
    if (i0 + 3 < M) {
        const int4 v = *reinterpret_cast<const int4*>(ray_id + i0);  // 16B aligned
        ids[0] = v.x; ids[1] = v.y; ids[2] = v.z; ids[3] = v.w;
    } else {
        #pragma unroll
        for (int k = 0; k < 4; ++k)
            ids[k] = (i0 + k < M) ? ray_id[i0 + k] : 0;
    }

    int prev = (i0 == 0) ? -1 : ray_id[i0 - 1];   // neighbor: L1/L2 hit

    #pragma unroll
    for (int k = 0; k < 4; ++k) {
        const int i = i0 + k;
        if (i < M) {
            const int cur = ids[k];
            for (int r = prev + 1; r <= cur; ++r) g_start[r] = i;  // ~0-1 iters
            prev = cur;
        }
    }

    // Thread that owns the last element seals the tail (incl. sentinel N).
    if (i0 <= M - 1 && M - 1 < i0 + 4) {
        const int last = ids[(M - 1) - i0];
        for (int r = last + 1; r <= N; ++r) g_start[r] = M;
    }
}

// ---------------------------------------------------------------------------
// Softplus with series fast path (x is deeply negative for this workload).
// ---------------------------------------------------------------------------
__device__ __forceinline__ float softplus_fast(float x)
{
    const float t = __expf(x);
    if (t < 0.04f) {
        // log1p(t) = t(1 - t/2 + t^2/3 - t^3/4), rel err <= t^4/5 ~ 5e-7
        return t * (1.0f + t * (-0.5f + t * (0.33333333f - 0.25f * t)));
    }
    return fmaxf(x, 0.0f) + log1pf(__expf(-fabsf(x)));  // exact stable fallback
}

__device__ __forceinline__ float expm1n_fast(float u)  // 1 - e^{-u}, u >= 0
{
    if (u < 0.03f) {
        // u(1 - u/2 + u^2/6), rel err ~1e-6
        return u * (1.0f + u * (-0.5f + u * 0.16666667f));
    }
    return 1.0f - __expf(-u);
}

// ---------------------------------------------------------------------------
// Pass 2: one warp per ray, 4 elements per lane (128-element chunks).
// Local 4-wide scan per lane + one warp shuffle-scan of lane totals.
// Full-chunk fast path: no per-element predication on the common path.
// ---------------------------------------------------------------------------
__global__ __launch_bounds__(256) void seg_scan_kernel(
    const float* __restrict__ density,
    float* __restrict__ out_weights,
    float* __restrict__ out_alphainv,
    int N)
{
    const int warps_per_block = blockDim.x >> 5;
    const int ray  = blockIdx.x * warps_per_block + (threadIdx.x >> 5);
    const int lane = threadIdx.x & 31;
    if (ray >= N) return;

    const int s = g_start[ray];
    const int e = g_start[ray + 1];

    float carry = 0.0f;   // inclusive prefix of sp entering this chunk

    for (int base = s; base < e; base += 128) {
        const int  i0   = base + lane * 4;
        const bool full = (base + 128 <= e);   // whole chunk in range

        float sp[4];
        if (full) {
            #pragma unroll
            for (int k = 0; k < 4; ++k)
                sp[k] = softplus_fast(density[i0 + k] + SHIFT_F);
        } else {
            #pragma unroll
            for (int k = 0; k < 4; ++k) {
                const int i = i0 + k;
                sp[k] = (i < e) ? softplus_fast(density[i] + SHIFT_F) : 0.0f;
            }
        }

        // Local inclusive scan (4-wide)
        const float inc0 = sp[0];
        const float inc1 = inc0 + sp[1];
        const float inc2 = inc1 + sp[2];
        const float inc3 = inc2 + sp[3];

        // Warp scan of lane totals
        float scan = inc3;
        #pragma unroll
        for (int d = 1; d < 32; d <<= 1) {
            const float v = __shfl_up_sync(0xffffffffu, scan, d);
            if (lane >= d) scan += v;
        }
        const float lane_excl = (scan - inc3) + carry;  // prefix before this lane

        const float exs[4] = {lane_excl,
                              lane_excl + inc0,
                              lane_excl + inc1,
                              lane_excl + inc2};

        if (full) {
            #pragma unroll
            for (int k = 0; k < 4; ++k) {
                const float T     = __expf(-exs[k] * INTERVAL_F);
                const float alpha = expm1n_fast(sp[k] * INTERVAL_F);
                out_weights[i0 + k] = alpha * T;
            }
        } else {
            #pragma unroll
            for (int k = 0; k < 4; ++k) {
                const int i = i0 + k;
                if (i < e) {
                    const float T     = __expf(-exs[k] * INTERVAL_F);
                    const float alpha = expm1n_fast(sp[k] * INTERVAL_F);
                    out_weights[i] = alpha * T;
                }
            }
        }

        carry += __shfl_sync(0xffffffffu, scan, 31);
    }

    if (lane == 0) {
        out_alphainv[ray] = __expf(-carry * INTERVAL_F);
    }
}

// ---------------------------------------------------------------------------
extern "C" void kernel_launch(void* const* d_in, const int* in_sizes, int n_in,
                              void* d_out, int out_size)
{
    const float* density = (const float*)d_in[0];
    const int*   ray_id  = (const int*)d_in[1];

    const int M = in_sizes[0];
    const int N = out_size - M;   // weights[M] ++ alphainv_last[N]

    float* out_weights  = (float*)d_out;
    float* out_alphainv = (float*)d_out + M;

    // Pass 1: boundaries (4 elems/thread)
    {
        const int threads = 256;
        const int quads   = (M + 3) / 4;
        const int blocks  = (quads + threads - 1) / threads;
        seg_bounds_kernel<<<blocks, threads>>>(ray_id, M, N);
    }

    // Pass 2: warp-per-ray segmented scan (4 elems/lane)
    {
        const int threads = 256;                 // 8 warps / block
        const int warps_per_block = threads / 32;
        const int blocks = (N + warps_per_block - 1) / warps_per_block;
        seg_scan_kernel<<<blocks, threads>>>(density, out_weights, out_alphainv, N);
    }
}

// round 5
// speedup vs baseline: 1.6184x; 1.1101x over previous
#include <cuda_runtime.h>
#include <cuda_bf16.h>

// DirectVoxGO Raw2Alpha + Alphas2Weights fused, sorted-segment version (R5).
//
// Key identity (INTERVAL = 0.5):
//   1 - alpha = exp(-softplus(x)/2) = (1 + e^x)^{-1/2}
// so transmittance is a running PRODUCT of om = (1+t)^{-1/2}, t = e^x.
// No per-element exp for T, no series for softplus, no final exp per ray.
//
// Inputs (metadata order):
//   d_in[0]: density  float32 [M]
//   d_in[1]: ray_id   int32   [M]   (sorted ascending)
// Output: d_out float32 [M + N] = concat(weights[M], alphainv_last[N])

#define SHIFT_F      (-9.2102403669758f)   // log(1/(1-1e-4) - 1)

#define MAX_RAYS_P1  (1 << 20)             // generous static bound for N+1

__device__ int g_start[MAX_RAYS_P1 + 1];

// ---------------------------------------------------------------------------
// Pass 1: segment boundaries, 8 elements per thread via 2x int4.
// Sortedness => if last id of the octet equals prev, the whole octet is
// boundary-free (one compare, ~94% of threads).
// ---------------------------------------------------------------------------
__global__ __launch_bounds__(256) void seg_bounds_kernel(
    const int* __restrict__ ray_id, int M, int N)
{
    const int t  = blockIdx.x * blockDim.x + threadIdx.x;
    const int i0 = t * 8;
    if (i0 >= M) return;

    int prev = (i0 == 0) ? -1 : __ldg(ray_id + i0 - 1);

    if (i0 + 8 <= M) {
        const int4 a = *reinterpret_cast<const int4*>(ray_id + i0);
        const int4 b = *reinterpret_cast<const int4*>(ray_id + i0 + 4);

        if (b.w != prev) {                       // at least one boundary here
            const int ids[8] = {a.x, a.y, a.z, a.w, b.x, b.y, b.z, b.w};
            #pragma unroll
            for (int k = 0; k < 8; ++k) {
                const int cur = ids[k];
                for (int r = prev + 1; r <= cur; ++r) g_start[r] = i0 + k;
                prev = cur;
            }
        }
        if (i0 + 8 == M) {                       // seal tail + sentinel
            for (int r = b.w + 1; r <= N; ++r) g_start[r] = M;
        }
    } else {
        #pragma unroll
        for (int k = 0; k < 8; ++k) {
            const int i = i0 + k;
            if (i < M) {
                const int cur = ray_id[i];
                for (int r = prev + 1; r <= cur; ++r) g_start[r] = i;
                prev = cur;
                if (i == M - 1)
                    for (int r = cur + 1; r <= N; ++r) g_start[r] = M;
            }
        }
    }
}

// ---------------------------------------------------------------------------
// alpha = 1 - (1+t)^{-1/2},  om = 1 - alpha,  t = e^x.
// Fast path: series in t (x deeply negative for this workload),
//   alpha = t(1/2 - 3/8 t + 5/16 t^2),  rel err <= ~4e-5 at t = 0.04.
// ---------------------------------------------------------------------------
__device__ __forceinline__ void alpha_om(float x, float& al, float& om)
{
    const float t = __expf(x);
    if (t < 0.04f) {
        al = t * (0.5f + t * (-0.375f + t * 0.3125f));
    } else {
        // exact stable fallback (vanishingly rare; also correct for t = inf)
        al = 1.0f - __expf(-0.5f * log1pf(t));
    }
    om = 1.0f - al;
}

// ---------------------------------------------------------------------------
// Pass 2: one warp per ray, 4 elements/lane, multiplicative segmented scan.
// Chunks are aligned DOWN to 4 (base0 = s & ~3): full-valid lanes use
// LDG.128/STG.128; ragged edge lanes take identity / guarded scalar path.
// ---------------------------------------------------------------------------
__global__ __launch_bounds__(256) void seg_scan_kernel(
    const float* __restrict__ density,
    float* __restrict__ out_weights,
    float* __restrict__ out_alphainv,
    int N)
{
    const int warps_per_block = blockDim.x >> 5;
    const int ray  = blockIdx.x * warps_per_block + (threadIdx.x >> 5);
    const int lane = threadIdx.x & 31;
    if (ray >= N) return;

    const int s = g_start[ray];
    const int e = g_start[ray + 1];

    float carryP = 1.0f;                 // transmittance entering current chunk
    const int base0 = s & ~3;            // 16B-aligned chunk origin

    for (int base = base0; base < e; base += 128) {
        const int  i0   = base + lane * 4;
        const bool allv = (i0 >= s) & (i0 + 4 <= e);

        float al[4], om[4];
        if (allv) {
            const float4 d = *reinterpret_cast<const float4*>(density + i0);
            alpha_om(d.x + SHIFT_F, al[0], om[0]);
            alpha_om(d.y + SHIFT_F, al[1], om[1]);
            alpha_om(d.z + SHIFT_F, al[2], om[2]);
            alpha_om(d.w + SHIFT_F, al[3], om[3]);
        } else {
            #pragma unroll
            for (int k = 0; k < 4; ++k) {
                const int i = i0 + k;
                if (i >= s && i < e) alpha_om(density[i] + SHIFT_F, al[k], om[k]);
                else                 { al[k] = 0.0f; om[k] = 1.0f; }
            }
        }

        // local inclusive products
        const float p0 = om[0];
        const float p1 = p0 * om[1];
        const float p2 = p1 * om[2];
        const float p3 = p2 * om[3];

        // warp inclusive product-scan of lane totals
        float scan = p3;
        #pragma unroll
        for (int d = 1; d < 32; d <<= 1) {
            const float v = __shfl_up_sync(0xffffffffu, scan, d);
            if (lane >= d) scan *= v;
        }

        // exclusive product entering this lane
        float Pex = __shfl_up_sync(0xffffffffu, scan, 1);
        Pex = (lane == 0) ? carryP : Pex * carryP;

        const float w0 = al[0] * Pex;
        const float w1 = al[1] * (Pex * p0);
        const float w2 = al[2] * (Pex * p1);
        const float w3 = al[3] * (Pex * p2);

        if (allv) {
            *reinterpret_cast<float4*>(out_weights + i0) =
                make_float4(w0, w1, w2, w3);
        } else {
            if (i0 + 0 >= s && i0 + 0 < e) out_weights[i0 + 0] = w0;
            if (i0 + 1 >= s && i0 + 1 < e) out_weights[i0 + 1] = w1;
            if (i0 + 2 >= s && i0 + 2 < e) out_weights[i0 + 2] = w2;
            if (i0 + 3 >= s && i0 + 3 < e) out_weights[i0 + 3] = w3;
        }

        carryP *= __shfl_sync(0xffffffffu, scan, 31);
    }

    if (lane == 0) {
        out_alphainv[ray] = carryP;      // = exp(-total_sp * 0.5) exactly
    }
}

// ---------------------------------------------------------------------------
extern "C" void kernel_launch(void* const* d_in, const int* in_sizes, int n_in,
                              void* d_out, int out_size)
{
    const float* density = (const float*)d_in[0];
    const int*   ray_id  = (const int*)d_in[1];

    const int M = in_sizes[0];
    const int N = out_size - M;   // weights[M] ++ alphainv_last[N]

    float* out_weights  = (float*)d_out;
    float* out_alphainv = (float*)d_out + M;

    // Pass 1: boundaries (8 elems/thread)
    {
        const int threads = 256;
        const int octs    = (M + 7) / 8;
        const int blocks  = (octs + threads - 1) / threads;
        seg_bounds_kernel<<<blocks, threads>>>(ray_id, M, N);
    }

    // Pass 2: warp-per-ray multiplicative segmented scan (4 elems/lane)
    {
        const int threads = 256;                 // 8 warps / block
        const int warps_per_block = threads / 32;
        const int blocks = (N + warps_per_block - 1) / warps_per_block;
        seg_scan_kernel<<<blocks, threads>>>(density, out_weights, out_alphainv, N);
    }
}